// round 5
// baseline (speedup 1.0000x reference)
#include <cuda_runtime.h>
#include <cuda_bf16.h>
#include <math.h>

// Problem shapes (fixed by the dataset)
#define PB 4        // batch
#define PT 2048     // seq
#define PD 1024     // d_model
#define PH 2048     // hidden
#define PR 1024     // repr
#define PV 2052     // vocab (2048+4)
#define PK 4        // codebooks
#define PM (PB*PT)  // 8192 tokens

// Scratch (device globals; no allocation allowed)
__device__ float g_xn[(size_t)PM * PD];   // 32 MB  normalized x
__device__ float g_h [(size_t)PM * PH];   // 64 MB  hidden (per-head, reused)
__device__ float g_g [(size_t)PM * PR];   // 32 MB  repr   (per-head, reused)
__device__ float g_c1[(size_t)PK * PH];   // folded LN-bias @ W1 + b1

// ---------------------------------------------------------------------------
// LayerNorm: one block per row of x[8192, 1024] -> g_xn (no affine; affine is
// folded into GEMM1's B-scale and the c1 bias vector).
// ---------------------------------------------------------------------------
__global__ __launch_bounds__(256) void ln_kernel(const float* __restrict__ x,
                                                 float* __restrict__ xn) {
    const int row = blockIdx.x;
    const float4* xr = (const float4*)(x + (size_t)row * PD);
    float4 v = xr[threadIdx.x];                  // 256 threads * 4 = 1024
    float s  = v.x + v.y + v.z + v.w;
    float s2 = v.x*v.x + v.y*v.y + v.z*v.z + v.w*v.w;

    #pragma unroll
    for (int o = 16; o; o >>= 1) {
        s  += __shfl_down_sync(0xFFFFFFFFu, s,  o);
        s2 += __shfl_down_sync(0xFFFFFFFFu, s2, o);
    }
    __shared__ float red[2][8];
    int wid = threadIdx.x >> 5, lane = threadIdx.x & 31;
    if (lane == 0) { red[0][wid] = s; red[1][wid] = s2; }
    __syncthreads();
    float ts = 0.f, ts2 = 0.f;
    #pragma unroll
    for (int w = 0; w < 8; w++) { ts += red[0][w]; ts2 += red[1][w]; }
    const float mu  = ts * (1.0f / PD);
    const float var = ts2 * (1.0f / PD) - mu * mu;
    const float inv = rsqrtf(var + 1e-5f);

    float4 o;
    o.x = (v.x - mu) * inv; o.y = (v.y - mu) * inv;
    o.z = (v.z - mu) * inv; o.w = (v.w - mu) * inv;
    ((float4*)(xn + (size_t)row * PD))[threadIdx.x] = o;
}

// ---------------------------------------------------------------------------
// c1[k,h] = b1[k,h] + sum_d ln_bias[k,d] * W1[k,d,h]
// ---------------------------------------------------------------------------
__global__ __launch_bounds__(256) void c1_kernel(const float* __restrict__ ln_bias,
                                                 const float* __restrict__ W1,
                                                 const float* __restrict__ b1,
                                                 float* __restrict__ c1) {
    const int k = blockIdx.y;
    const int h = blockIdx.x * blockDim.x + threadIdx.x;
    const float* lb = ln_bias + (size_t)k * PD;
    const float* w  = W1 + (size_t)k * PD * PH + h;
    float s = b1[(size_t)k * PH + h];
    #pragma unroll 4
    for (int d = 0; d < PD; d++) s += lb[d] * w[(size_t)d * PH];
    c1[(size_t)k * PH + h] = s;
}

// ---------------------------------------------------------------------------
// Generic fused fp32 GEMM: C[M,N] = A[M,Kc] @ B[Kc,N] (+bias) (+gelu)
//   SCALE_B : multiply B row d by bscale[d] (folds LN scale into W1)
//   GELU    : exact erf GELU epilogue
//   SPLIT   : scatter rows into [B,K,T,V] layout at head k_head
//   NCHECK  : N not a multiple of 128 (classifier, N=2052; N%4==0 holds)
// 128x128 tile, BK=16, 256 threads, 8x8 per-thread register block.
// ---------------------------------------------------------------------------
#define BM 128
#define BN 128
#define BK 16

template<bool SCALE_B, bool GELU, bool SPLIT, bool NCHECK>
__global__ __launch_bounds__(256, 2)
void gemm_fused(const float* __restrict__ A, const float* __restrict__ B,
                const float* __restrict__ bscale, const float* __restrict__ bias,
                float* __restrict__ C, int M, int N, int Kc, int k_head) {
    __shared__ float As[BK][BM];
    __shared__ float Bs[BK][BN];

    const int tid = threadIdx.x;
    const int m0 = blockIdx.y * BM;
    const int n0 = blockIdx.x * BN;
    const int tx = tid & 15;     // N direction
    const int ty = tid >> 4;     // M direction

    // A staging: 128x16 tile, float4 per thread, stored transposed
    const int a_row = tid >> 2;          // 0..63
    const int a_col = (tid & 3) * 4;     // 0,4,8,12
    // B staging: 16x128 tile, float4 per thread
    const int b_row = tid >> 5;          // 0..7
    const int b_col = (tid & 31) * 4;    // 0..124

    float acc[8][8] = {};

    for (int k0 = 0; k0 < Kc; k0 += BK) {
        #pragma unroll
        for (int h = 0; h < 2; h++) {
            const int r = a_row + h * 64;
            const float4 av = *(const float4*)(A + (size_t)(m0 + r) * Kc + k0 + a_col);
            As[a_col + 0][r] = av.x;
            As[a_col + 1][r] = av.y;
            As[a_col + 2][r] = av.z;
            As[a_col + 3][r] = av.w;
        }
        #pragma unroll
        for (int h = 0; h < 2; h++) {
            const int r = b_row + h * 8;
            const int n = n0 + b_col;
            float4 bv = make_float4(0.f, 0.f, 0.f, 0.f);
            if (!NCHECK || n < N)   // N%4==0 -> float4 fully in or fully out
                bv = *(const float4*)(B + (size_t)(k0 + r) * N + n);
            if (SCALE_B) {
                const float sc = bscale[k0 + r];
                bv.x *= sc; bv.y *= sc; bv.z *= sc; bv.w *= sc;
            }
            *(float4*)&Bs[r][b_col] = bv;
        }
        __syncthreads();

        #pragma unroll
        for (int kk = 0; kk < BK; kk++) {
            const float4 a0 = *(const float4*)&As[kk][ty * 8];
            const float4 a1 = *(const float4*)&As[kk][ty * 8 + 4];
            const float4 b0 = *(const float4*)&Bs[kk][tx * 8];
            const float4 b1 = *(const float4*)&Bs[kk][tx * 8 + 4];
            const float af[8] = {a0.x, a0.y, a0.z, a0.w, a1.x, a1.y, a1.z, a1.w};
            const float bf[8] = {b0.x, b0.y, b0.z, b0.w, b1.x, b1.y, b1.z, b1.w};
            #pragma unroll
            for (int i = 0; i < 8; i++)
                #pragma unroll
                for (int j = 0; j < 8; j++)
                    acc[i][j] += af[i] * bf[j];
        }
        __syncthreads();
    }

    #pragma unroll
    for (int i = 0; i < 8; i++) {
        const int cm = m0 + ty * 8 + i;
        float* crow;
        if (SPLIT) {
            const int b = cm >> 11;        // / T (2048)
            const int t = cm & (PT - 1);
            crow = C + ((size_t)(b * PK + k_head) * PT + t) * (size_t)N;
        } else {
            crow = C + (size_t)cm * N;
        }
        #pragma unroll
        for (int j = 0; j < 8; j++) {
            const int cn = n0 + tx * 8 + j;
            if (!NCHECK || cn < N) {
                float v = acc[i][j] + bias[cn];
                if (GELU) v = 0.5f * v * (1.0f + erff(v * 0.70710678118654752f));
                crow[cn] = v;
            }
        }
    }
}

// ---------------------------------------------------------------------------
extern "C" void kernel_launch(void* const* d_in, const int* in_sizes, int n_in,
                              void* d_out, int out_size) {
    const float* x        = (const float*)d_in[0];
    const float* ln_scale = (const float*)d_in[1];
    const float* ln_bias  = (const float*)d_in[2];
    const float* W1       = (const float*)d_in[3];
    const float* b1       = (const float*)d_in[4];
    const float* W2       = (const float*)d_in[5];
    const float* b2       = (const float*)d_in[6];
    const float* Wc       = (const float*)d_in[7];
    const float* bc       = (const float*)d_in[8];
    float* out = (float*)d_out;

    float *xn, *hbuf, *gbuf, *c1;
    cudaGetSymbolAddress((void**)&xn,   g_xn);
    cudaGetSymbolAddress((void**)&hbuf, g_h);
    cudaGetSymbolAddress((void**)&gbuf, g_g);
    cudaGetSymbolAddress((void**)&c1,   g_c1);

    ln_kernel<<<PM, 256>>>(x, xn);
    c1_kernel<<<dim3(PH / 256, PK), 256>>>(ln_bias, W1, b1, c1);

    for (int k = 0; k < PK; k++) {
        // h = gelu( xn @ (diag(ln_scale_k) * W1_k) + c1_k )
        gemm_fused<true, true, false, false>
            <<<dim3(PH / BN, PM / BM), 256>>>(
                xn, W1 + (size_t)k * PD * PH, ln_scale + (size_t)k * PD,
                c1 + (size_t)k * PH, hbuf, PM, PH, PD, k);
        // g = h @ W2_k + b2_k
        gemm_fused<false, false, false, false>
            <<<dim3(PR / BN, PM / BM), 256>>>(
                hbuf, W2 + (size_t)k * PH * PR, nullptr,
                b2 + (size_t)k * PR, gbuf, PM, PR, PH, k);
        // logits[:,k,:,:] = g @ Wc_k + bc_k   (strided [B,K,T,V] output)
        gemm_fused<false, false, true, true>
            <<<dim3((PV + BN - 1) / BN, PM / BM), 256>>>(
                gbuf, Wc + (size_t)k * PR * PV, nullptr,
                bc + (size_t)k * PV, out, PM, PV, PR, k);
    }
}